// round 1
// baseline (speedup 1.0000x reference)
#include <cuda_runtime.h>
#include <cuda_bf16.h>
#include <math.h>

#define NPTS     12288
#define DIM      64
#define CDIM     3
#define KNN      85
#define SAMPLE_N 2000
#define HALF_N   6144
#define GAMMA    0.5f

// ---------------- device scratch (no allocations allowed) ----------------
__device__ unsigned long long g_packed1[NPTS];
__device__ unsigned long long g_packed2[NPTS];
__device__ int    g_sample_idx[SAMPLE_N];
__device__ float  g_coordsT[CDIM * NPTS];      // [c][n]
__device__ float  g_embsT[DIM * SAMPLE_N];     // [d][s]
__device__ float  g_csampT[CDIM * SAMPLE_N];   // [c][s]
__device__ double g_acc[6];  // se, sc, see, scc, sec, local_sum

// ---------------- threefry2x32-20 (matches JAX) ----------------
__host__ __device__ __forceinline__ unsigned int rotl32(unsigned int x, int d) {
    return (x << d) | (x >> (32 - d));
}

__host__ __device__ __forceinline__ void tf2x32(unsigned int k0, unsigned int k1,
                                                unsigned int x0, unsigned int x1,
                                                unsigned int& y0, unsigned int& y1) {
    unsigned int ks0 = k0, ks1 = k1, ks2 = k0 ^ k1 ^ 0x1BD11BDAu;
    x0 += ks0; x1 += ks1;
#define TF_RND(r) { x0 += x1; x1 = rotl32(x1, (r)); x1 ^= x0; }
    TF_RND(13) TF_RND(15) TF_RND(26) TF_RND(6)
    x0 += ks1; x1 += ks2 + 1u;
    TF_RND(17) TF_RND(29) TF_RND(16) TF_RND(24)
    x0 += ks2; x1 += ks0 + 2u;
    TF_RND(13) TF_RND(15) TF_RND(26) TF_RND(6)
    x0 += ks0; x1 += ks1 + 3u;
    TF_RND(17) TF_RND(29) TF_RND(16) TF_RND(24)
    x0 += ks1; x1 += ks2 + 4u;
    TF_RND(13) TF_RND(15) TF_RND(26) TF_RND(6)
    x0 += ks2; x1 += ks0 + 5u;
#undef TF_RND
    y0 = x0; y1 = x1;
}

// ---------------- init ----------------
__global__ void init_kernel() {
    if (threadIdx.x < 6) g_acc[threadIdx.x] = 0.0;
}

// ---------------- permutation via rank (== stable sort by (bits, pos)) ----------------
// Round-1 sort keys: threefry(subkey1, iota(12288)) with JAX's original halves layout:
// lane l processes (l, l+6144) -> bits[l]=y0, bits[l+6144]=y1.
__global__ void permA_kernel(unsigned int k0, unsigned int k1) {
    int l = blockIdx.x * blockDim.x + threadIdx.x;
    if (l < HALF_N) {
        unsigned int y0, y1;
        tf2x32(k0, k1, (unsigned int)l, (unsigned int)(l + HALF_N), y0, y1);
        g_packed1[l]          = ((unsigned long long)y0 << 14) | (unsigned int)l;
        g_packed1[l + HALF_N] = ((unsigned long long)y1 << 14) | (unsigned int)(l + HALF_N);
    }
}

// rank of mykey among 12288 unique keys; tiled through smem (broadcast reads)
__device__ int rank12288(const unsigned long long* keys, unsigned long long mykey) {
    __shared__ unsigned long long tile[256];
    int cnt = 0;
    for (int base = 0; base < NPTS; base += 256) {
        tile[threadIdx.x] = keys[base + threadIdx.x];
        __syncthreads();
#pragma unroll 8
        for (int u = 0; u < 256; u++) cnt += (tile[u] < mykey) ? 1 : 0;
        __syncthreads();
    }
    return cnt;
}

// Round-2 keys are generated per *position* (r = rank after round 1).
__global__ void permB_kernel(unsigned int k0, unsigned int k1) {
    int j = blockIdx.x * blockDim.x + threadIdx.x;  // 12288 threads exactly
    unsigned long long mk = g_packed1[j];
    int r = rank12288(g_packed1, mk);
    int lane = (r < HALF_N) ? r : (r - HALF_N);
    unsigned int y0, y1;
    tf2x32(k0, k1, (unsigned int)lane, (unsigned int)(lane + HALF_N), y0, y1);
    unsigned int bits = (r < HALF_N) ? y0 : y1;
    g_packed2[j] = ((unsigned long long)bits << 14) | (unsigned int)r;
}

__global__ void permC_kernel() {
    int j = blockIdx.x * blockDim.x + threadIdx.x;
    unsigned long long mk = g_packed2[j];
    int r2 = rank12288(g_packed2, mk);
    if (r2 < SAMPLE_N) g_sample_idx[r2] = j;
}

// ---------------- gather / transpose ----------------
__global__ void gather_kernel(const float* __restrict__ emb, const float* __restrict__ coords) {
    int stride = gridDim.x * blockDim.x;
    int gid = blockIdx.x * blockDim.x + threadIdx.x;
    // coordsT[c][n]
    for (int t = gid; t < CDIM * NPTS; t += stride) {
        int c = t / NPTS, n = t - c * NPTS;
        g_coordsT[t] = coords[n * CDIM + c];
    }
    // embsT[d][s]  (coalesced read per sampled row, scattered write)
    for (int t = gid; t < SAMPLE_N * DIM; t += stride) {
        int s = t / DIM, d = t - s * DIM;
        g_embsT[d * SAMPLE_N + s] = emb[(long)g_sample_idx[s] * DIM + d];
    }
    // csampT[c][s]
    for (int t = gid; t < SAMPLE_N * CDIM; t += stride) {
        int s = t / CDIM, c = t - s * CDIM;
        g_csampT[c * SAMPLE_N + s] = coords[(long)g_sample_idx[s] * CDIM + c];
    }
}

// ---------------- reductions ----------------
__device__ void block_reduce_atomic(double v, double* target, double* swarp) {
    int lane = threadIdx.x & 31, wid = threadIdx.x >> 5;
#pragma unroll
    for (int o = 16; o > 0; o >>= 1) v += __shfl_down_sync(0xffffffffu, v, o);
    if (lane == 0) swarp[wid] = v;
    __syncthreads();
    if (wid == 0) {
        double r = (lane < 8) ? swarp[lane] : 0.0;
#pragma unroll
        for (int o = 4; o > 0; o >>= 1) r += __shfl_down_sync(0xffffffffu, r, o);
        if (lane == 0) atomicAdd(target, r);
    }
    __syncthreads();
}

// ---------------- pearson sums over 2000x2000 pairs ----------------
#define TI 8
__global__ void pearson_kernel(const float* __restrict__ emb, const float* __restrict__ coords) {
    __shared__ float semb[TI][DIM];
    __shared__ float scrd[TI][CDIM];
    __shared__ double swarp[8];
    int i0 = blockIdx.x * TI;
    for (int t = threadIdx.x; t < TI * DIM; t += blockDim.x) {
        int r = t / DIM, d = t - r * DIM;
        semb[r][d] = emb[(long)g_sample_idx[i0 + r] * DIM + d];
    }
    for (int t = threadIdx.x; t < TI * CDIM; t += blockDim.x) {
        int r = t / CDIM, c = t - r * CDIM;
        scrd[r][c] = coords[(long)g_sample_idx[i0 + r] * CDIM + c];
    }
    __syncthreads();

    double se = 0, sc = 0, see = 0, scc = 0, sec = 0;
    for (int j = threadIdx.x; j < SAMPLE_N; j += blockDim.x) {
        float sq[TI];
#pragma unroll
        for (int r = 0; r < TI; r++) sq[r] = 0.f;
#pragma unroll 4
        for (int d = 0; d < DIM; d++) {
            float ej = g_embsT[d * SAMPLE_N + j];
#pragma unroll
            for (int r = 0; r < TI; r++) {
                float df = semb[r][d] - ej;
                sq[r] = fmaf(df, df, sq[r]);
            }
        }
        float cj0 = g_csampT[j];
        float cj1 = g_csampT[SAMPLE_N + j];
        float cj2 = g_csampT[2 * SAMPLE_N + j];
#pragma unroll
        for (int r = 0; r < TI; r++) {
            float d0 = scrd[r][0] - cj0, d1 = scrd[r][1] - cj1, d2 = scrd[r][2] - cj2;
            float cd = sqrtf(fmaf(d0, d0, fmaf(d1, d1, d2 * d2)));
            float ed = sqrtf(sq[r]);
            se += (double)ed;
            sc += (double)cd;
            see += (double)ed * (double)ed;
            scc += (double)cd * (double)cd;
            sec += (double)ed * (double)cd;
        }
    }
    block_reduce_atomic(se,  &g_acc[0], swarp);
    block_reduce_atomic(sc,  &g_acc[1], swarp);
    block_reduce_atomic(see, &g_acc[2], swarp);
    block_reduce_atomic(scc, &g_acc[3], swarp);
    block_reduce_atomic(sec, &g_acc[4], swarp);
}

// ---------------- KNN + local loss ----------------
__global__ void knn_kernel(const float* __restrict__ emb, const float* __restrict__ coords) {
    extern __shared__ float sdist[];       // NPTS floats
    __shared__ float ei[DIM];
    __shared__ int s_warp[8];
    __shared__ int s_cnt;
    __shared__ double swarpd[8];

    int i = blockIdx.x;
    int tid = threadIdx.x;
    float ci0 = coords[3 * i + 0], ci1 = coords[3 * i + 1], ci2 = coords[3 * i + 2];
    if (tid < DIM) ei[tid] = emb[(long)i * DIM + tid];

    for (int j = tid; j < NPTS; j += 256) {
        float d0 = ci0 - g_coordsT[j];
        float d1 = ci1 - g_coordsT[NPTS + j];
        float d2 = ci2 - g_coordsT[2 * NPTS + j];
        sdist[j] = sqrtf(fmaf(d0, d0, fmaf(d1, d1, d2 * d2)));
    }
    __syncthreads();

    // binary search on float bit patterns for the (K+1)-th smallest (incl. self at 0)
    unsigned int lo = 0u, hi = 0x7F800000u;
    while (lo < hi) {
        unsigned int mid = (lo + hi) >> 1;
        int c = 0;
        for (int j = tid; j < NPTS; j += 256)
            c += (__float_as_uint(sdist[j]) <= mid) ? 1 : 0;
#pragma unroll
        for (int o = 16; o > 0; o >>= 1) c += __shfl_down_sync(0xffffffffu, c, o);
        if ((tid & 31) == 0) s_warp[tid >> 5] = c;
        __syncthreads();
        if (tid == 0) {
            int tot = 0;
#pragma unroll
            for (int w = 0; w < 8; w++) tot += s_warp[w];
            s_cnt = tot;
        }
        __syncthreads();
        if (s_cnt >= KNN + 1) hi = mid; else lo = mid + 1;
    }
    unsigned int tau = lo;

    double acc = 0.0;
    for (int j = tid; j < NPTS; j += 256) {
        float t = sdist[j];
        if (__float_as_uint(t) <= tau && j != i) {
            const float* ej = emb + (long)j * DIM;
            float sq = 0.f;
#pragma unroll
            for (int d = 0; d < DIM; d++) {
                float df = ei[d] - ej[d];
                sq = fmaf(df, df, sq);
            }
            float p = sqrtf(sq);
            float diff = p - t;
            acc += (double)(diff * diff * expf(-GAMMA * t));
        }
    }
    block_reduce_atomic(acc, &g_acc[5], swarpd);
}

// ---------------- finalize ----------------
__global__ void finalize_kernel(float* out) {
    double M = (double)SAMPLE_N * (double)SAMPLE_N;
    double se = g_acc[0], sc = g_acc[1], see = g_acc[2], scc = g_acc[3], sec = g_acc[4];
    double ls = g_acc[5];
    double me = se / M, mc = sc / M;
    double cov = sec / M - me * mc;
    double ve = see / M - me * me;
    double vc = scc / M - mc * mc;
    double es = sqrt(ve + 1e-8);
    double cs = sqrt(vc + 1e-8);
    double pearson = cov / (es * cs + 1e-8);
    double local = ls / ((double)NPTS * (double)KNN);
    out[0] = (float)((1.0 - pearson) + 0.5 * local);
}

// ---------------- launch ----------------
extern "C" void kernel_launch(void* const* d_in, const int* in_sizes, int n_in,
                              void* d_out, int out_size) {
    const float* emb;
    const float* coords;
    if (in_sizes[0] == NPTS * DIM) {
        emb = (const float*)d_in[0];
        coords = (const float*)d_in[1];
    } else {
        emb = (const float*)d_in[1];
        coords = (const float*)d_in[0];
    }
    float* out = (float*)d_out;

    // JAX: key = [0, 42]; two rounds, each: keys = split(key); key=keys[0], subkey=keys[1]
    // split (original impl): threefry(key, iota(4)) -> lanes (0,2),(1,3);
    // keyA=(y0_lane0, y0_lane1), keyB=(y1_lane0, y1_lane1)
    unsigned int a0, b0, a1, b1;
    tf2x32(0u, 42u, 0u, 2u, a0, b0);
    tf2x32(0u, 42u, 1u, 3u, a1, b1);
    unsigned int c0, d0, c1, d1;
    tf2x32(a0, a1, 0u, 2u, c0, d0);
    tf2x32(a0, a1, 1u, 3u, c1, d1);
    // subkey round1 = (b0, b1); subkey round2 = (d0, d1)

    init_kernel<<<1, 32>>>();
    permA_kernel<<<HALF_N / 256, 256>>>(b0, b1);
    permB_kernel<<<NPTS / 256, 256>>>(d0, d1);
    permC_kernel<<<NPTS / 256, 256>>>();
    gather_kernel<<<160, 256>>>(emb, coords);
    pearson_kernel<<<SAMPLE_N / TI, 256>>>(emb, coords);

    cudaFuncSetAttribute(knn_kernel, cudaFuncAttributeMaxDynamicSharedMemorySize,
                         NPTS * (int)sizeof(float));
    knn_kernel<<<NPTS, 256, NPTS * sizeof(float)>>>(emb, coords);

    finalize_kernel<<<1, 1>>>(out);
}

// round 2
// speedup vs baseline: 2.1527x; 2.1527x over previous
#include <cuda_runtime.h>
#include <cuda_bf16.h>
#include <math.h>

#define NPTS     12288
#define DIM      64
#define CDIM     3
#define KNN      85
#define SAMPLE_N 2000
#define HALF_N   6144
#define GAMMA    0.5f
#define RPB      2
#define SEG      8
#define SEGLEN   (NPTS / SEG)   // 1536

// ---------------- device scratch ----------------
__device__ unsigned long long g_packed1[NPTS];
__device__ unsigned long long g_packed2[NPTS];
__device__ int    g_rank1[NPTS];
__device__ int    g_rank2[NPTS];
__device__ int    g_sample_idx[SAMPLE_N];
__device__ float4 g_coords4[NPTS];
__device__ float  g_embsT[DIM * SAMPLE_N];     // [d][s]
__device__ float  g_csampT[CDIM * SAMPLE_N];   // [c][s]
__device__ double g_acc[6];  // se, sc, see, scc, sec, local_sum

// ---------------- threefry2x32-20 ----------------
__host__ __device__ __forceinline__ unsigned int rotl32(unsigned int x, int d) {
    return (x << d) | (x >> (32 - d));
}

__host__ __device__ __forceinline__ void tf2x32(unsigned int k0, unsigned int k1,
                                                unsigned int x0, unsigned int x1,
                                                unsigned int& y0, unsigned int& y1) {
    unsigned int ks0 = k0, ks1 = k1, ks2 = k0 ^ k1 ^ 0x1BD11BDAu;
    x0 += ks0; x1 += ks1;
#define TF_RND(r) { x0 += x1; x1 = rotl32(x1, (r)); x1 ^= x0; }
    TF_RND(13) TF_RND(15) TF_RND(26) TF_RND(6)
    x0 += ks1; x1 += ks2 + 1u;
    TF_RND(17) TF_RND(29) TF_RND(16) TF_RND(24)
    x0 += ks2; x1 += ks0 + 2u;
    TF_RND(13) TF_RND(15) TF_RND(26) TF_RND(6)
    x0 += ks0; x1 += ks1 + 3u;
    TF_RND(17) TF_RND(29) TF_RND(16) TF_RND(24)
    x0 += ks1; x1 += ks2 + 4u;
    TF_RND(13) TF_RND(15) TF_RND(26) TF_RND(6)
    x0 += ks2; x1 += ks0 + 5u;
#undef TF_RND
    y0 = x0; y1 = x1;
}

// ---------------- init ----------------
__global__ void init_kernel() {
    int g = blockIdx.x * blockDim.x + threadIdx.x;
    if (g < NPTS) { g_rank1[g] = 0; g_rank2[g] = 0; }
    if (g < 6) g_acc[g] = 0.0;
}

// ---------------- permutation via rank ----------------
__global__ void permA_kernel(unsigned int k0, unsigned int k1) {
    int l = blockIdx.x * blockDim.x + threadIdx.x;
    if (l < HALF_N) {
        unsigned int y0, y1;
        tf2x32(k0, k1, (unsigned int)l, (unsigned int)(l + HALF_N), y0, y1);
        g_packed1[l]          = ((unsigned long long)y0 << 14) | (unsigned int)l;
        g_packed1[l + HALF_N] = ((unsigned long long)y1 << 14) | (unsigned int)(l + HALF_N);
    }
}

// partial rank: block (bx, by) counts segment by for 256 keys of block bx
__global__ void rank_partial_kernel(const unsigned long long* __restrict__ keys,
                                    int* __restrict__ rank) {
    __shared__ unsigned long long tile[256];
    int j = blockIdx.x * 256 + threadIdx.x;
    unsigned long long mk = keys[j];
    int base0 = blockIdx.y * SEGLEN;
    int cnt = 0;
    for (int base = base0; base < base0 + SEGLEN; base += 256) {
        tile[threadIdx.x] = keys[base + threadIdx.x];
        __syncthreads();
#pragma unroll 8
        for (int u = 0; u < 256; u++) cnt += (tile[u] < mk) ? 1 : 0;
        __syncthreads();
    }
    atomicAdd(&rank[j], cnt);
}

__global__ void permB_gen_kernel(unsigned int k0, unsigned int k1) {
    int j = blockIdx.x * blockDim.x + threadIdx.x;
    int r = g_rank1[j];
    int lane = (r < HALF_N) ? r : (r - HALF_N);
    unsigned int y0, y1;
    tf2x32(k0, k1, (unsigned int)lane, (unsigned int)(lane + HALF_N), y0, y1);
    unsigned int bits = (r < HALF_N) ? y0 : y1;
    g_packed2[j] = ((unsigned long long)bits << 14) | (unsigned int)r;
}

__global__ void permC_gen_kernel() {
    int j = blockIdx.x * blockDim.x + threadIdx.x;
    int r2 = g_rank2[j];
    if (r2 < SAMPLE_N) g_sample_idx[r2] = j;
}

// ---------------- gather / transpose ----------------
__global__ void gather_kernel(const float* __restrict__ emb, const float* __restrict__ coords) {
    int stride = gridDim.x * blockDim.x;
    int gid = blockIdx.x * blockDim.x + threadIdx.x;
    for (int t = gid; t < NPTS; t += stride) {
        g_coords4[t] = make_float4(coords[3 * t], coords[3 * t + 1], coords[3 * t + 2], 0.f);
    }
    for (int t = gid; t < SAMPLE_N * DIM; t += stride) {
        int s = t / DIM, d = t - s * DIM;
        g_embsT[d * SAMPLE_N + s] = emb[(long)g_sample_idx[s] * DIM + d];
    }
    for (int t = gid; t < SAMPLE_N * CDIM; t += stride) {
        int s = t / CDIM, c = t - s * CDIM;
        g_csampT[c * SAMPLE_N + s] = coords[(long)g_sample_idx[s] * CDIM + c];
    }
}

// ---------------- reductions ----------------
__device__ void block_reduce_atomic(double v, double* target, double* swarp) {
    int lane = threadIdx.x & 31, wid = threadIdx.x >> 5;
#pragma unroll
    for (int o = 16; o > 0; o >>= 1) v += __shfl_down_sync(0xffffffffu, v, o);
    if (lane == 0) swarp[wid] = v;
    __syncthreads();
    if (wid == 0) {
        double r = (lane < 8) ? swarp[lane] : 0.0;
#pragma unroll
        for (int o = 4; o > 0; o >>= 1) r += __shfl_down_sync(0xffffffffu, r, o);
        if (lane == 0) atomicAdd(target, r);
    }
    __syncthreads();
}

// ---------------- pearson sums over 2000x2000 pairs ----------------
#define TI 8
__global__ void pearson_kernel(const float* __restrict__ emb, const float* __restrict__ coords) {
    __shared__ float semb[TI][DIM];
    __shared__ float scrd[TI][CDIM];
    __shared__ double swarp[8];
    int i0 = blockIdx.x * TI;
    for (int t = threadIdx.x; t < TI * DIM; t += blockDim.x) {
        int r = t / DIM, d = t - r * DIM;
        semb[r][d] = emb[(long)g_sample_idx[i0 + r] * DIM + d];
    }
    for (int t = threadIdx.x; t < TI * CDIM; t += blockDim.x) {
        int r = t / CDIM, c = t - r * CDIM;
        scrd[r][c] = coords[(long)g_sample_idx[i0 + r] * CDIM + c];
    }
    __syncthreads();

    double se = 0, sc = 0, see = 0, scc = 0, sec = 0;
    for (int j = threadIdx.x; j < SAMPLE_N; j += blockDim.x) {
        float sq[TI];
#pragma unroll
        for (int r = 0; r < TI; r++) sq[r] = 0.f;
#pragma unroll 4
        for (int d = 0; d < DIM; d++) {
            float ej = g_embsT[d * SAMPLE_N + j];
#pragma unroll
            for (int r = 0; r < TI; r++) {
                float df = semb[r][d] - ej;
                sq[r] = fmaf(df, df, sq[r]);
            }
        }
        float cj0 = g_csampT[j];
        float cj1 = g_csampT[SAMPLE_N + j];
        float cj2 = g_csampT[2 * SAMPLE_N + j];
#pragma unroll
        for (int r = 0; r < TI; r++) {
            float d0 = scrd[r][0] - cj0, d1 = scrd[r][1] - cj1, d2 = scrd[r][2] - cj2;
            float cd = sqrtf(fmaf(d0, d0, fmaf(d1, d1, d2 * d2)));
            float ed = sqrtf(sq[r]);
            se += (double)ed;
            sc += (double)cd;
            see += (double)ed * (double)ed;
            scc += (double)cd * (double)cd;
            sec += (double)ed * (double)cd;
        }
    }
    block_reduce_atomic(se,  &g_acc[0], swarp);
    block_reduce_atomic(sc,  &g_acc[1], swarp);
    block_reduce_atomic(see, &g_acc[2], swarp);
    block_reduce_atomic(scc, &g_acc[3], swarp);
    block_reduce_atomic(sec, &g_acc[4], swarp);
}

// ---------------- histogram rank-select helper ----------------
// Finds smallest bin where cumulative count >= rank over 2048 bins.
// Writes bin to *s_bin and exclusive cumulative-before to *s_cum.
__device__ __forceinline__ void hist_select(const int* hist, int rank, int* wsum,
                                            int* s_bin, int* s_cum) {
    int t = threadIdx.x;
    int lane = t & 31, wid = t >> 5;
    int base = t * 8;
    int h[8];
    int s = 0;
#pragma unroll
    for (int u = 0; u < 8; u++) { h[u] = hist[base + u]; s += h[u]; }
    int v = s;
#pragma unroll
    for (int o = 1; o < 32; o <<= 1) {
        int n = __shfl_up_sync(0xffffffffu, v, o);
        if (lane >= o) v += n;
    }
    if (lane == 31) wsum[wid] = v;
    __syncthreads();
    int woff = 0;
#pragma unroll
    for (int w = 0; w < 8; w++) woff += (w < wid) ? wsum[w] : 0;
    int incl = woff + v;
    int excl = incl - s;
    if (excl < rank && rank <= incl) {
        int c = excl;
#pragma unroll
        for (int u = 0; u < 8; u++) {
            if (rank <= c + h[u]) { *s_bin = base + u; *s_cum = c; break; }
            c += h[u];
        }
    }
    __syncthreads();
}

// ---------------- KNN + local loss (RPB rows per block) ----------------
__global__ void knn_kernel(const float* __restrict__ emb, const float* __restrict__ coords) {
    extern __shared__ float sd[];            // [RPB][NPTS] squared distances
    __shared__ int hist[2048];
    __shared__ int wsum[8];
    __shared__ int s_bin, s_cum;
    __shared__ float ei[RPB][DIM];
    __shared__ double swarpd[8];

    int tid = threadIdx.x;
    int i0 = blockIdx.x * RPB;

    float qx[RPB], qy[RPB], qz[RPB];
#pragma unroll
    for (int r = 0; r < RPB; r++) {
        qx[r] = __ldg(&coords[3 * (i0 + r) + 0]);
        qy[r] = __ldg(&coords[3 * (i0 + r) + 1]);
        qz[r] = __ldg(&coords[3 * (i0 + r) + 2]);
    }
    if (tid < RPB * DIM) {
        int r = tid / DIM, d = tid - r * DIM;
        ei[r][d] = emb[(long)(i0 + r) * DIM + d];
    }

    // distance pass (one coord load serves both rows)
    for (int j = tid; j < NPTS; j += 256) {
        float4 c = g_coords4[j];
#pragma unroll
        for (int r = 0; r < RPB; r++) {
            float dx = qx[r] - c.x, dy = qy[r] - c.y, dz = qz[r] - c.z;
            sd[r * NPTS + j] = fmaf(dx, dx, fmaf(dy, dy, dz * dz));
        }
    }
    for (int k = tid; k < 2048; k += 256) hist[k] = 0;
    __syncthreads();

    unsigned int tau[RPB];
    for (int r = 0; r < RPB; r++) {
        const float* sdr = sd + r * NPTS;
        // level 1: bins = float bits >> 20 (all finite positives map < 2048)
        for (int j = tid; j < NPTS; j += 256)
            atomicAdd(&hist[__float_as_uint(sdr[j]) >> 20], 1);
        __syncthreads();
        hist_select(hist, KNN + 1, wsum, &s_bin, &s_cum);
        int b1 = s_bin;
        int rank = (KNN + 1) - s_cum;
        for (int k = tid; k < 2048; k += 256) hist[k] = 0;
        __syncthreads();
        // level 2: bits >> 9 & 2047 within bucket b1
        for (int j = tid; j < NPTS; j += 256) {
            unsigned int bits = __float_as_uint(sdr[j]);
            if ((int)(bits >> 20) == b1) atomicAdd(&hist[(bits >> 9) & 2047], 1);
        }
        __syncthreads();
        hist_select(hist, rank, wsum, &s_bin, &s_cum);
        int b2 = s_bin;
        rank -= s_cum;
        for (int k = tid; k < 2048; k += 256) hist[k] = 0;
        __syncthreads();
        // level 3: low 9 bits within (b1,b2)
        unsigned int pre = ((unsigned int)b1 << 11) | (unsigned int)b2;
        for (int j = tid; j < NPTS; j += 256) {
            unsigned int bits = __float_as_uint(sdr[j]);
            if ((bits >> 9) == pre) atomicAdd(&hist[bits & 511], 1);
        }
        __syncthreads();
        hist_select(hist, rank, wsum, &s_bin, &s_cum);
        tau[r] = (pre << 9) | (unsigned int)s_bin;
        if (r + 1 < RPB) {
            for (int k = tid; k < 2048; k += 256) hist[k] = 0;
            __syncthreads();
        }
    }

    // accumulation over selected neighbors
    double acc = 0.0;
    for (int j = tid; j < NPTS; j += 256) {
#pragma unroll
        for (int r = 0; r < RPB; r++) {
            unsigned int bits = __float_as_uint(sd[r * NPTS + j]);
            if (bits <= tau[r] && j != i0 + r) {
                float t = sqrtf(__uint_as_float(bits));
                const float4* e4 = (const float4*)(emb + (long)j * DIM);
                const float4* a4 = (const float4*)(&ei[r][0]);
                float s = 0.f;
#pragma unroll
                for (int u = 0; u < DIM / 4; u++) {
                    float4 a = a4[u];
                    float4 b = e4[u];
                    float d0 = a.x - b.x, d1 = a.y - b.y, d2 = a.z - b.z, d3 = a.w - b.w;
                    s = fmaf(d0, d0, fmaf(d1, d1, fmaf(d2, d2, fmaf(d3, d3, s))));
                }
                float p = sqrtf(s);
                float df = p - t;
                acc += (double)(df * df * expf(-GAMMA * t));
            }
        }
    }
    block_reduce_atomic(acc, &g_acc[5], swarpd);
}

// ---------------- finalize ----------------
__global__ void finalize_kernel(float* out) {
    double M = (double)SAMPLE_N * (double)SAMPLE_N;
    double se = g_acc[0], sc = g_acc[1], see = g_acc[2], scc = g_acc[3], sec = g_acc[4];
    double ls = g_acc[5];
    double me = se / M, mc = sc / M;
    double cov = sec / M - me * mc;
    double ve = see / M - me * me;
    double vc = scc / M - mc * mc;
    double es = sqrt(ve + 1e-8);
    double cs = sqrt(vc + 1e-8);
    double pearson = cov / (es * cs + 1e-8);
    double local = ls / ((double)NPTS * (double)KNN);
    out[0] = (float)((1.0 - pearson) + 0.5 * local);
}

// ---------------- launch ----------------
extern "C" void kernel_launch(void* const* d_in, const int* in_sizes, int n_in,
                              void* d_out, int out_size) {
    const float* emb;
    const float* coords;
    if (in_sizes[0] == NPTS * DIM) {
        emb = (const float*)d_in[0];
        coords = (const float*)d_in[1];
    } else {
        emb = (const float*)d_in[1];
        coords = (const float*)d_in[0];
    }
    float* out = (float*)d_out;

    // JAX threefry key schedule: key=[0,42]; two rounds of split
    unsigned int a0, b0, a1, b1;
    tf2x32(0u, 42u, 0u, 2u, a0, b0);
    tf2x32(0u, 42u, 1u, 3u, a1, b1);
    unsigned int c0, d0, c1, d1;
    tf2x32(a0, a1, 0u, 2u, c0, d0);
    tf2x32(a0, a1, 1u, 3u, c1, d1);

    init_kernel<<<NPTS / 256, 256>>>();
    permA_kernel<<<HALF_N / 256, 256>>>(b0, b1);
    {
        unsigned long long* p1; cudaGetSymbolAddress((void**)&p1, g_packed1);
        unsigned long long* p2; cudaGetSymbolAddress((void**)&p2, g_packed2);
        int* r1; cudaGetSymbolAddress((void**)&r1, g_rank1);
        int* r2; cudaGetSymbolAddress((void**)&r2, g_rank2);
        dim3 rg(NPTS / 256, SEG);
        rank_partial_kernel<<<rg, 256>>>(p1, r1);
        permB_gen_kernel<<<NPTS / 256, 256>>>(d0, d1);
        rank_partial_kernel<<<rg, 256>>>(p2, r2);
        permC_gen_kernel<<<NPTS / 256, 256>>>();
    }
    gather_kernel<<<160, 256>>>(emb, coords);
    pearson_kernel<<<SAMPLE_N / TI, 256>>>(emb, coords);

    cudaFuncSetAttribute(knn_kernel, cudaFuncAttributeMaxDynamicSharedMemorySize,
                         RPB * NPTS * (int)sizeof(float));
    knn_kernel<<<NPTS / RPB, 256, RPB * NPTS * sizeof(float)>>>(emb, coords);

    finalize_kernel<<<1, 1>>>(out);
}